// round 16
// baseline (speedup 1.0000x reference)
#include <cuda_runtime.h>
#include <cuda_bf16.h>
#include <math.h>
#include <stdint.h>

// ---------------- problem constants ----------------
#define BB   2
#define TT   1024
#define HID  2048
#define NKH  8
#define NVH  16
#define DK   64
#define DV   128
#define KSZ  4
#define KD   (NKH*DK)          // 512
#define VD   (NVH*DV)          // 2048
#define CD   (2*KD + VD)       // 3072
#define IPD  (CD + VD + 2*NVH) // 5152
#define BT   (BB*TT)           // 2048
#define EPSR 1e-6f
#define SCALE 0.125f           // DK^-0.5
#define CS   64                // chunk size
#define NCH  (TT/CS)           // 16 chunks per sequence
#define NU   (BB*NVH*NCH)      // 512 units

// ---------------- scratch (__device__ globals; no allocs allowed) ----------------
__device__ float g_proj [(size_t)BT * IPD];
__device__ float g_q    [(size_t)BT * KD];
__device__ float g_k    [(size_t)BT * KD];
__device__ float g_v    [(size_t)BT * VD];
__device__ float g_beta [(size_t)BT * NVH];
__device__ float g_gdec [(size_t)BT * NVH];
__device__ float g_o    [(size_t)BT * VD];

// chunked-recurrence precomputed operands (per unit u = (b,h,c))
__device__ float g_kgt [(size_t)NU * 4096];   // [k][i] = k_i[k] * e^{G_i}
__device__ float g_tbt [(size_t)NU * 4096];   // [j][i] = T_ij * beta_j
__device__ float g_aqt [(size_t)NU * 4096];   // [i][j] = SCALE*(q_i.k_j)e^{Gi-Gj}, j<=i
__device__ float g_qgt [(size_t)NU * 4096];   // [k][i] = SCALE * q_i[k] * e^{G_i}
__device__ float g_kcm [(size_t)NU * 4096];   // [j][k] = k_j[k] * e^{G_C - G_j}
__device__ float g_tvm [(size_t)NU * 8192];   // [i][v] = (T B V)[i][v]
__device__ float g_egc [NU];

// bf16 hi/lo split operands for tensor-core GEMMs
__device__ __nv_bfloat16 g_xh [(size_t)BT * HID];
__device__ __nv_bfloat16 g_xl [(size_t)BT * HID];
__device__ __nv_bfloat16 g_wih[(size_t)IPD * HID];
__device__ __nv_bfloat16 g_wil[(size_t)IPD * HID];
__device__ __nv_bfloat16 g_woh[(size_t)HID * VD];
__device__ __nv_bfloat16 g_wol[(size_t)HID * VD];
__device__ __nv_bfloat16 g_gh [(size_t)BT * VD];
__device__ __nv_bfloat16 g_gl [(size_t)BT * VD];

__device__ __forceinline__ float silu_f(float x) { return x / (1.f + expf(-x)); }

// ---------------- packed f32x2 helpers ----------------
__device__ __forceinline__ unsigned long long pack2(float lo, float hi) {
    unsigned long long r;
    asm("mov.b64 %0, {%1, %2};" : "=l"(r) : "f"(lo), "f"(hi));
    return r;
}
__device__ __forceinline__ void ffma2(unsigned long long &d, unsigned long long a, unsigned long long b) {
    asm("fma.rn.f32x2 %0, %1, %2, %0;" : "+l"(d) : "l"(a), "l"(b));
}
__device__ __forceinline__ float lo2(unsigned long long v) { return __uint_as_float((unsigned)(v & 0xffffffffull)); }
__device__ __forceinline__ float hi2(unsigned long long v) { return __uint_as_float((unsigned)(v >> 32)); }

// ---------------- HMMA / ldmatrix / cp.async helpers (sm_80+ ISA) ----------------
__device__ __forceinline__ uint32_t smem_u32(const void* p) {
    uint32_t a;
    asm("{ .reg .u64 t; cvta.to.shared.u64 t, %1; cvt.u32.u64 %0, t; }" : "=r"(a) : "l"(p));
    return a;
}
__device__ __forceinline__ void ldsm_x4(uint32_t* r, uint32_t addr) {
    asm volatile("ldmatrix.sync.aligned.m8n8.x4.shared.b16 {%0,%1,%2,%3}, [%4];"
        : "=r"(r[0]), "=r"(r[1]), "=r"(r[2]), "=r"(r[3]) : "r"(addr));
}
__device__ __forceinline__ void mma_bf16(float* c, const uint32_t* a, const uint32_t* b) {
    asm volatile(
        "mma.sync.aligned.m16n8k16.row.col.f32.bf16.bf16.f32 "
        "{%0,%1,%2,%3}, {%4,%5,%6,%7}, {%8,%9}, {%0,%1,%2,%3};"
        : "+f"(c[0]), "+f"(c[1]), "+f"(c[2]), "+f"(c[3])
        : "r"(a[0]), "r"(a[1]), "r"(a[2]), "r"(a[3]), "r"(b[0]), "r"(b[1]));
}
__device__ __forceinline__ void cpa16(uint32_t dst, const void* src) {
    asm volatile("cp.async.cg.shared.global [%0], [%1], 16;" :: "r"(dst), "l"(src));
}
#define CP_COMMIT() asm volatile("cp.async.commit_group;" ::: "memory")
#define CP_WAIT5()  asm volatile("cp.async.wait_group 5;" ::: "memory")
#define CP_WAIT2()  asm volatile("cp.async.wait_group 2;" ::: "memory")
#define CP_WAIT1()  asm volatile("cp.async.wait_group 1;" ::: "memory")
#define CP_WAIT0()  asm volatile("cp.async.wait_group 0;" ::: "memory")

// ============ fp32 -> bf16 hi/lo split (fused: x, in_proj_w, out_proj_w) ============
#define NX  (BT*HID)            // 4,194,304
#define NWI (IPD*HID)           // 10,551,296
#define NWO (HID*VD)            // 4,194,304
#define NSPLIT (NX + NWI + NWO)

__global__ __launch_bounds__(256)
void split_all_kernel(const float* __restrict__ x, const float* __restrict__ wi,
                      const float* __restrict__ wo)
{
    int i = blockIdx.x * blockDim.x + threadIdx.x;
    const float* src;
    __nv_bfloat16 *hi, *lo;
    int off;
    if (i < NX)            { src = x;  hi = g_xh;  lo = g_xl;  off = i; }
    else if (i < NX + NWI) { src = wi; hi = g_wih; lo = g_wil; off = i - NX; }
    else if (i < NSPLIT)   { src = wo; hi = g_woh; lo = g_wol; off = i - NX - NWI; }
    else return;
    float v = src[off];
    __nv_bfloat16 h = __float2bfloat16(v);
    hi[off] = h;
    lo[off] = __float2bfloat16(v - __bfloat162float(h));
}

// ============ tensor-core GEMM: C[M,N] = A[M,K] @ B[N,K]^T (bf16 hi/lo split) ============
// tile 128x128x32, 8 warps (32m x 64n each), 6-stage cp.async pipeline,
// XOR-swizzled 64B-row smem stages (32KB/stage). 1 CTA/SM (192KB smem).
#define MTS    8192
#define OFF_AH 0
#define OFF_AL MTS
#define OFF_BH (2*MTS)
#define OFF_BL (3*MTS)
#define STG    (4*MTS)
#define NSTG   6
#define GSMEM  (NSTG*STG)                // 196608 B

__device__ __forceinline__ uint32_t swz(int r, int c) {
    return (uint32_t)(r * 64 + ((c ^ ((r >> 1) & 3)) * 16));
}

__global__ __launch_bounds__(256, 1)
void gemm_bf16split_kernel(const __nv_bfloat16* __restrict__ Ah, const __nv_bfloat16* __restrict__ Al,
                           const __nv_bfloat16* __restrict__ Bh, const __nv_bfloat16* __restrict__ Bl,
                           float* __restrict__ C, int M, int N, int K)
{
    extern __shared__ __align__(128) char smem[];
    const uint32_t sbase = smem_u32(smem);
    const int tid  = threadIdx.x;
    const int wid  = tid >> 5, lane = tid & 31;
    const int bm = blockIdx.y * 128;
    const int bn = blockIdx.x * 128;
    const int wm = (wid & 3) * 32;
    const int wn = (wid >> 2) * 64;

    float acc[2][8][4];
#pragma unroll
    for (int i = 0; i < 2; i++)
#pragma unroll
        for (int j = 0; j < 8; j++)
#pragma unroll
            for (int c = 0; c < 4; c++) acc[i][j][c] = 0.f;

    const int ns = K / 32;   // both call sites: ns = 64 >= NSTG

    auto load_stage = [&](int buf, int kbase) {
        const uint32_t sb0 = sbase + buf * STG;
#pragma unroll
        for (int it = 0; it < 2; it++) {
            int idx = tid + 256 * it;
            int row = idx >> 2, c = idx & 3;
            uint32_t soff = swz(row, c);
            const size_t ao = (size_t)(bm + row) * K + kbase + c * 8;
            cpa16(sb0 + OFF_AH + soff, Ah + ao);
            cpa16(sb0 + OFF_AL + soff, Al + ao);
            int br = bn + row; if (br >= N) br = 0;
            const size_t bo = (size_t)br * K + kbase + c * 8;
            cpa16(sb0 + OFF_BH + soff, Bh + bo);
            cpa16(sb0 + OFF_BL + soff, Bl + bo);
        }
    };

#pragma unroll
    for (int p = 0; p < NSTG; p++) { load_stage(p, p * 32); CP_COMMIT(); }

    const int arow  = lane & 15;
    const int acol8 = (lane >> 4) * 8;
    const int brow  = (lane & 7) + ((lane >> 4) & 1) * 8;
    const int bcol8 = ((lane >> 3) & 1) * 8;

    int buf = 0;
    for (int s = 0; s < ns; s++) {
        CP_WAIT5();
        __syncthreads();
        const uint32_t sb0 = sbase + buf * STG;
        const uint32_t sah = sb0 + OFF_AH, sal = sb0 + OFF_AL;
        const uint32_t sbh = sb0 + OFF_BH, sbl = sb0 + OFF_BL;

#pragma unroll
        for (int ks = 0; ks < 32; ks += 16) {
            uint32_t ah[2][4], al[2][4];
#pragma unroll
            for (int mt = 0; mt < 2; mt++) {
                int r = wm + mt * 16 + arow;
                uint32_t aoff = swz(r, (ks + acol8) >> 3);
                ldsm_x4(ah[mt], sah + aoff);
                ldsm_x4(al[mt], sal + aoff);
            }
#pragma unroll
            for (int ng = 0; ng < 4; ng++) {
                uint32_t bh[4], bl[4];
                int rb = wn + ng * 16 + brow;
                uint32_t boff = swz(rb, (ks + bcol8) >> 3);
                ldsm_x4(bh, sbh + boff);
                ldsm_x4(bl, sbl + boff);
#pragma unroll
                for (int mt = 0; mt < 2; mt++) {
                    float* c0 = acc[mt][ng * 2 + 0];
                    float* c1 = acc[mt][ng * 2 + 1];
                    mma_bf16(c0, ah[mt], bh + 0);
                    mma_bf16(c0, ah[mt], bl + 0);
                    mma_bf16(c0, al[mt], bh + 0);
                    mma_bf16(c1, ah[mt], bh + 2);
                    mma_bf16(c1, ah[mt], bl + 2);
                    mma_bf16(c1, al[mt], bh + 2);
                }
            }
        }
        __syncthreads();
        if (s + NSTG < ns) load_stage(buf, (s + NSTG) * 32);
        CP_COMMIT();
        if (++buf == NSTG) buf = 0;
    }

#pragma unroll
    for (int mt = 0; mt < 2; mt++) {
        int r0 = bm + wm + mt * 16 + (lane >> 2);
        int r1 = r0 + 8;
#pragma unroll
        for (int nt = 0; nt < 8; nt++) {
            int col = bn + wn + nt * 8 + (lane & 3) * 2;
            if (col < N) {
                float* a = acc[mt][nt];
                *(float2*)(C + (size_t)r0 * N + col) = make_float2(a[0], a[1]);
                *(float2*)(C + (size_t)r1 * N + col) = make_float2(a[2], a[3]);
            }
        }
    }
}

// ============ conv(q,k) + silu + l2norm, and beta/g scalars ============
__global__ __launch_bounds__(512)
void conv_qk_kernel(const float* __restrict__ proj, const float* __restrict__ conv_w,
                    const float* __restrict__ A_log, const float* __restrict__ dt_bias,
                    float* __restrict__ qo, float* __restrict__ ko,
                    float* __restrict__ beta_o, float* __restrict__ g_o_)
{
    const int bt = blockIdx.x;
    const int t  = bt & (TT - 1);
    const int warp = threadIdx.x >> 5, lane = threadIdx.x & 31;

    float r[2];
#pragma unroll
    for (int s = 0; s < 2; s++) {
        int ch = warp * 64 + s * 32 + lane;
        float acc = 0.f;
#pragma unroll
        for (int kk = 0; kk < KSZ; kk++) {
            int tt = t - 3 + kk;
            float xv = (tt >= 0) ? proj[(size_t)(bt - 3 + kk) * IPD + ch] : 0.f;
            acc = fmaf(xv, conv_w[ch * KSZ + kk], acc);
        }
        r[s] = silu_f(acc);
    }
    float ss = r[0]*r[0] + r[1]*r[1];
#pragma unroll
    for (int o = 16; o; o >>= 1) ss += __shfl_xor_sync(0xffffffffu, ss, o);
    float inv = 1.f / fmaxf(sqrtf(ss), 1e-12f);

    if (warp < 8) {
        float* dst = qo + ((size_t)bt * NKH + warp) * DK;
        dst[lane] = r[0] * inv; dst[lane + 32] = r[1] * inv;
    } else {
        float* dst = ko + ((size_t)bt * NKH + (warp - 8)) * DK;
        dst[lane] = r[0] * inv; dst[lane + 32] = r[1] * inv;
    }

    if (threadIdx.x < NVH) {
        int h = threadIdx.x;
        float braw = proj[(size_t)bt * IPD + CD + VD + h];
        float araw = proj[(size_t)bt * IPD + CD + VD + NVH + h];
        beta_o[bt * NVH + h] = 1.f / (1.f + expf(-braw));
        float si = araw + dt_bias[h];
        float sp = (si > 20.f) ? si : log1pf(expf(si));
        g_o_[bt * NVH + h] = -expf(A_log[h]) * sp;
    }
}

// ============ conv(v) + silu ============
__global__ __launch_bounds__(256)
void conv_v_kernel(const float* __restrict__ proj, const float* __restrict__ conv_w,
                   float* __restrict__ vo)
{
    int idx = blockIdx.x * blockDim.x + threadIdx.x;
    int cv = idx & (VD - 1);
    int bt = idx >> 11;
    int t  = bt & (TT - 1);
    int ch = 2 * KD + cv;
    float acc = 0.f;
#pragma unroll
    for (int kk = 0; kk < KSZ; kk++) {
        int tt = t - 3 + kk;
        float xv = (tt >= 0) ? proj[(size_t)(bt - 3 + kk) * IPD + ch] : 0.f;
        acc = fmaf(xv, conv_w[ch * KSZ + kk], acc);
    }
    vo[idx] = silu_f(acc);
}

// ============ Phase A: per-(b,h,chunk) precompute (fully parallel) [proven] ============
#define PA_SMEM (20864 * 4)

__global__ __launch_bounds__(256)
void chunk_prep_kernel(const float* __restrict__ qarr, const float* __restrict__ karr,
                       const float* __restrict__ varr, const float* __restrict__ garr,
                       const float* __restrict__ barr)
{
    extern __shared__ __align__(16) float sm[];
    float* KT   = sm;
    float* QT   = sm + 4096;
    float* Lm   = sm + 8192;
    float* Tm   = sm + 12352;
    float* TBTs = sm + 16512;
    float* gsh  = sm + 20608;
    float* bsh  = sm + 20672;
    float* Gs   = sm + 20736;
    float* egs  = sm + 20800;
    float* Vs   = sm;

    const int u  = blockIdx.x;
    const int c  = u & 15;
    const int h  = (u >> 4) & 15;
    const int b  = u >> 8;
    const int kh = h >> 1;
    const int t0 = b * TT + c * CS;
    const int tid = threadIdx.x;
    const size_t ub  = (size_t)u * 4096;
    const size_t ub2 = (size_t)u * 8192;

    {
        int i = tid & 63, kq = (tid >> 6) * 16;
        const float* krow = karr + ((size_t)(t0 + i) * NKH + kh) * DK;
        const float* qrow = qarr + ((size_t)(t0 + i) * NKH + kh) * DK;
#pragma unroll
        for (int m = 0; m < 16; m += 4) {
            float4 kv = *(const float4*)(krow + kq + m);
            float4 qv = *(const float4*)(qrow + kq + m);
            KT[(kq+m+0)*64 + i] = kv.x; KT[(kq+m+1)*64 + i] = kv.y;
            KT[(kq+m+2)*64 + i] = kv.z; KT[(kq+m+3)*64 + i] = kv.w;
            QT[(kq+m+0)*64 + i] = qv.x; QT[(kq+m+1)*64 + i] = qv.y;
            QT[(kq+m+2)*64 + i] = qv.z; QT[(kq+m+3)*64 + i] = qv.w;
        }
        if (tid < 64) {
            gsh[tid] = garr[(size_t)(t0 + tid) * NVH + h];
            bsh[tid] = barr[(size_t)(t0 + tid) * NVH + h];
        }
    }
    __syncthreads();
    if (tid == 0) {
        float s = 0.f;
        for (int i = 0; i < 64; i++) { s += gsh[i]; Gs[i] = s; }
    }
    __syncthreads();
    if (tid < 64) egs[tid] = expf(Gs[tid]);
    __syncthreads();

    const int ty = tid >> 4, tx = tid & 15;

    {
        float mm[16], aq[16];
#pragma unroll
        for (int z = 0; z < 16; z++) { mm[z] = 0.f; aq[z] = 0.f; }
        for (int k = 0; k < 64; k++) {
            float4 ka = *(const float4*)&KT[k*64 + 4*ty];
            float4 kb = *(const float4*)&KT[k*64 + 4*tx];
            float4 qa = *(const float4*)&QT[k*64 + 4*ty];
#pragma unroll
            for (int r2 = 0; r2 < 4; r2++) {
                float av = (&ka.x)[r2], qv = (&qa.x)[r2];
                mm[r2*4+0] = fmaf(av, kb.x, mm[r2*4+0]);
                mm[r2*4+1] = fmaf(av, kb.y, mm[r2*4+1]);
                mm[r2*4+2] = fmaf(av, kb.z, mm[r2*4+2]);
                mm[r2*4+3] = fmaf(av, kb.w, mm[r2*4+3]);
                aq[r2*4+0] = fmaf(qv, kb.x, aq[r2*4+0]);
                aq[r2*4+1] = fmaf(qv, kb.y, aq[r2*4+1]);
                aq[r2*4+2] = fmaf(qv, kb.z, aq[r2*4+2]);
                aq[r2*4+3] = fmaf(qv, kb.w, aq[r2*4+3]);
            }
        }
#pragma unroll
        for (int r2 = 0; r2 < 4; r2++) {
            int i = 4*ty + r2;
            float ov[4];
#pragma unroll
            for (int c2 = 0; c2 < 4; c2++) {
                int j = 4*tx + c2;
                float e = expf(fminf(Gs[i] - Gs[j], 0.f));
                Lm[i*65 + j] = (j < i) ? bsh[i] * mm[r2*4+c2] * e : 0.f;
                ov[c2] = (j <= i) ? SCALE * aq[r2*4+c2] * e : 0.f;
            }
            *(float4*)&g_aqt[ub + (size_t)i*64 + 4*tx] = make_float4(ov[0], ov[1], ov[2], ov[3]);
        }
    }

    {
        int i = tid & 63, kq = (tid >> 6) * 16;
        float ei = egs[i];
#pragma unroll
        for (int m = 0; m < 16; m++) {
            g_kgt[ub + (size_t)(kq+m)*64 + i] = KT[(kq+m)*64 + i] * ei;
            g_qgt[ub + (size_t)(kq+m)*64 + i] = QT[(kq+m)*64 + i] * (SCALE * ei);
        }
        int j = tid >> 2, kq2 = (tid & 3) * 16;
        float sc2 = expf(Gs[63] - Gs[j]);
        const float* krow = karr + ((size_t)(t0 + j) * NKH + kh) * DK;
#pragma unroll
        for (int m = 0; m < 16; m += 4) {
            float4 kv = *(const float4*)(krow + kq2 + m);
            *(float4*)&g_kcm[ub + (size_t)j*64 + kq2 + m] =
                make_float4(kv.x * sc2, kv.y * sc2, kv.z * sc2, kv.w * sc2);
        }
        if (tid == 0) g_egc[u] = expf(Gs[63]);
    }

    for (int idx = tid; idx < 4096; idx += 256) {
        int i = idx >> 6, j = idx & 63;
        Tm[i*65 + j] = (i == j) ? 1.f : 0.f;
    }
    for (int r = 0; r < 63; r++) {
        __syncthreads();
        int i = r + 1 + (tid >> 2);
        if (i < 64) {
            float lir = Lm[i*65 + r];
            for (int j = (tid & 3); j <= r; j += 4)
                Tm[i*65 + j] -= lir * Tm[r*65 + j];
        }
    }
    __syncthreads();

    {
        int i = tid & 63, jq = (tid >> 6) * 16;
#pragma unroll
        for (int m = 0; m < 16; m++) {
            int j = jq + m;
            float tv = Tm[i*65 + j] * bsh[j];
            TBTs[j*64 + i] = tv;
            g_tbt[ub + (size_t)j*64 + i] = tv;
        }
    }
    __syncthreads();

    {
        int j = tid >> 1, v0 = (tid & 1) * 64;
        const float* vrow = varr + (size_t)(t0 + j) * VD + h * DV + v0;
#pragma unroll
        for (int m = 0; m < 64; m += 4) {
            *(float4*)&Vs[j*128 + v0 + m] = *(const float4*)(vrow + m);
        }
    }
    __syncthreads();

    for (int half = 0; half < 2; half++) {
        float acc[16];
#pragma unroll
        for (int z = 0; z < 16; z++) acc[z] = 0.f;
        for (int j = 0; j < 64; j++) {
            float4 a = *(const float4*)&TBTs[j*64 + 4*ty];
            float4 bv = *(const float4*)&Vs[j*128 + half*64 + 4*tx];
#pragma unroll
            for (int r2 = 0; r2 < 4; r2++) {
                float av = (&a.x)[r2];
                acc[r2*4+0] = fmaf(av, bv.x, acc[r2*4+0]);
                acc[r2*4+1] = fmaf(av, bv.y, acc[r2*4+1]);
                acc[r2*4+2] = fmaf(av, bv.z, acc[r2*4+2]);
                acc[r2*4+3] = fmaf(av, bv.w, acc[r2*4+3]);
            }
        }
#pragma unroll
        for (int r2 = 0; r2 < 4; r2++) {
            int i = 4*ty + r2;
            *(float4*)&g_tvm[ub2 + (size_t)i*128 + half*64 + 4*tx] =
                make_float4(acc[r2*4+0], acc[r2*4+1], acc[r2*4+2], acc[r2*4+3]);
        }
    }
}

// ============ Phase B: chunk scan, fused 3 passes, 5 operand slots [R15-proven] ============
#define SC_SMEM ((2048*4 + 4096*3 + 4352 + 4096) * 4)   // 28928 floats = 115712 B

__global__ __launch_bounds__(256)
void chunk_scan_kernel(float* __restrict__ oarr)
{
    extern __shared__ __align__(16) float ssm[];
    float* Ssh  = ssm;            // 64x32
    float* Wsh  = ssm + 2048;
    float* Dsh  = ssm + 4096;
    float* TVsh = ssm + 6144;
    float* SA   = ssm + 8192;     // kgt
    float* SB   = ssm + 12288;    // qgt
    float* SC   = ssm + 16384;    // tbt
    float* SD   = ssm + 20480;    // aqt (pitch 68, 4352 floats)
    float* SE   = ssm + 24832;    // kcm

    const int bid = blockIdx.x;
    const int vs = bid & 3;
    const int h  = (bid >> 2) & 15;
    const int b  = bid >> 6;
    const int v0 = vs * 32;
    const int tid = threadIdx.x;
    const int ty = tid >> 3;
    const int tx = tid & 7;

    auto stage64 = [&](float* dst, const float* src) {
        uint32_t d = smem_u32(dst);
#pragma unroll
        for (int r = 0; r < 4; r++) { int id = tid + 256*r; cpa16(d + id*16, src + (size_t)id*4); }
    };
    auto stage68 = [&](float* dst, const float* src) {
        uint32_t d = smem_u32(dst);
#pragma unroll
        for (int r = 0; r < 4; r++) {
            int id = tid + 256*r; int row = id >> 4, cc = id & 15;
            cpa16(d + (row*68 + cc*4)*4, src + (size_t)id*4);
        }
    };
    auto stageTV = [&](const float* src) {
        uint32_t d = smem_u32(TVsh);
#pragma unroll
        for (int r = 0; r < 2; r++) {
            int id = tid + 256*r; int row = id >> 3, cc = id & 7;
            cpa16(d + id*16, src + (size_t)row*128 + cc*4);
        }
    };

    for (int idx = tid; idx < 2048; idx += 256) Ssh[idx] = 0.f;

    const size_t ubase = (size_t)(((b << 4) | h) << 4) * 4096;
    const size_t ub2base = ubase * 2;

    stage64(SA, g_kgt + ubase);
    stage64(SB, g_qgt + ubase);
    CP_COMMIT();
    stage64(SC, g_tbt + ubase);
    stageTV(g_tvm + ub2base + v0);
    CP_COMMIT();
    stage68(SD, g_aqt + ubase);
    stage64(SE, g_kcm + ubase);
    CP_COMMIT();

    for (int c = 0; c < NCH; c++) {
        const size_t u    = (size_t)((((b << 4) | h) << 4) | c);
        const size_t ubn  = (u + 1) * 4096;
        const size_t ub2n = (u + 1) * 8192;
        const bool more = (c + 1 < NCH);

        CP_WAIT2();
        __syncthreads();

        unsigned long long o00=0,o01=0,o10=0,o11=0;
        {
            unsigned long long w00=0,w01=0,w10=0,w11=0;
            for (int k = 0; k < 64; k++) {
                float2 kg = *(const float2*)&SA[k*64 + 2*ty];
                float2 qg = *(const float2*)&SB[k*64 + 2*ty];
                const unsigned long long* bp = (const unsigned long long*)&Ssh[k*32 + 4*tx];
                unsigned long long s0 = bp[0], s1 = bp[1];
                unsigned long long kx = pack2(kg.x, kg.x), ky = pack2(kg.y, kg.y);
                unsigned long long qx = pack2(qg.x, qg.x), qy = pack2(qg.y, qg.y);
                ffma2(w00, kx, s0); ffma2(w01, kx, s1);
                ffma2(w10, ky, s0); ffma2(w11, ky, s1);
                ffma2(o00, qx, s0); ffma2(o01, qx, s1);
                ffma2(o10, qy, s0); ffma2(o11, qy, s1);
            }
            unsigned long long* w0 = (unsigned long long*)&Wsh[(2*ty)*32 + 4*tx];
            unsigned long long* w1 = (unsigned long long*)&Wsh[(2*ty+1)*32 + 4*tx];
            w0[0]=w00; w0[1]=w01; w1[0]=w10; w1[1]=w11;
        }

        CP_WAIT1();
        __syncthreads();
        if (more) { stage64(SA, g_kgt + ubn); stage64(SB, g_qgt + ubn); }
        CP_COMMIT();

        {
            unsigned long long a00=0,a01=0,a10=0,a11=0;
            for (int k = 0; k < 64; k++) {
                float2 tb = *(const float2*)&SC[k*64 + 2*ty];
                const unsigned long long* bp = (const unsigned long long*)&Wsh[k*32 + 4*tx];
                unsigned long long b0 = bp[0], b1 = bp[1];
                unsigned long long ax = pack2(tb.x, tb.x), ay = pack2(tb.y, tb.y);
                ffma2(a00, ax, b0); ffma2(a01, ax, b1);
                ffma2(a10, ay, b0); ffma2(a11, ay, b1);
            }
            float4 t0 = *(const float4*)&TVsh[(2*ty)*32 + 4*tx];
            float4 t1 = *(const float4*)&TVsh[(2*ty+1)*32 + 4*tx];
            *(float4*)&Dsh[(2*ty)*32 + 4*tx] =
                make_float4(t0.x - lo2(a00), t0.y - hi2(a00), t0.z - lo2(a01), t0.w - hi2(a01));
            *(float4*)&Dsh[(2*ty+1)*32 + 4*tx] =
                make_float4(t1.x - lo2(a10), t1.y - hi2(a10), t1.z - lo2(a11), t1.w - hi2(a11));
        }

        CP_WAIT1();
        __syncthreads();
        if (more) { stage64(SC, g_tbt + ubn); stageTV(g_tvm + ub2n + v0); }
        CP_COMMIT();

        {
            unsigned long long s00=0,s01=0,s10=0,s11=0;
            for (int j = 0; j < 64; j++) {
                float aq0 = SD[(2*ty)*68 + j];
                float aq1 = SD[(2*ty+1)*68 + j];
                float2 kc = *(const float2*)&SE[j*64 + 2*ty];
                const unsigned long long* bp = (const unsigned long long*)&Dsh[j*32 + 4*tx];
                unsigned long long d0 = bp[0], d1 = bp[1];
                unsigned long long a0 = pack2(aq0, aq0), a1 = pack2(aq1, aq1);
                unsigned long long k0 = pack2(kc.x, kc.x), k1 = pack2(kc.y, kc.y);
                ffma2(o00, a0, d0); ffma2(o01, a0, d1);
                ffma2(o10, a1, d0); ffma2(o11, a1, d1);
                ffma2(s00, k0, d0); ffma2(s01, k0, d1);
                ffma2(s10, k1, d0); ffma2(s11, k1, d1);
            }
            int trow = b * TT + c * CS + 2*ty;
            *(float4*)(oarr + (size_t)trow * VD + h * DV + v0 + 4*tx) =
                make_float4(lo2(o00), hi2(o00), lo2(o01), hi2(o01));
            *(float4*)(oarr + (size_t)(trow+1) * VD + h * DV + v0 + 4*tx) =
                make_float4(lo2(o10), hi2(o10), lo2(o11), hi2(o11));

            float eg = g_egc[u];
            unsigned long long eg2 = pack2(eg, eg);
            unsigned long long* sp0 = (unsigned long long*)&Ssh[(2*ty)*32 + 4*tx];
            unsigned long long* sp1 = (unsigned long long*)&Ssh[(2*ty+1)*32 + 4*tx];
            ffma2(s00, eg2, sp0[0]); ffma2(s01, eg2, sp0[1]);
            ffma2(s10, eg2, sp1[0]); ffma2(s11, eg2, sp1[1]);
            sp0[0]=s00; sp0[1]=s01; sp1[0]=s10; sp1[1]=s11;
        }

        __syncthreads();
        if (more) { stage68(SD, g_aqt + ubn); stage64(SE, g_kcm + ubn); }
        CP_COMMIT();
    }
    CP_WAIT0();
}

// ============ RMSNorm * silu(z) gate -> bf16 hi/lo ============
__global__ __launch_bounds__(256)
void gate_kernel(const float* __restrict__ o, const float* __restrict__ proj,
                 const float* __restrict__ nw,
                 __nv_bfloat16* __restrict__ gh, __nv_bfloat16* __restrict__ gl)
{
    int gw = (blockIdx.x * blockDim.x + threadIdx.x) >> 5;
    int lane = threadIdx.x & 31;
    int h  = gw & 15;
    int bt = gw >> 4;

    const float* orow = o + (size_t)bt * VD + h * DV;
    float v[4]; float ss = 0.f;
#pragma unroll
    for (int s = 0; s < 4; s++) { v[s] = orow[lane + 32 * s]; ss = fmaf(v[s], v[s], ss); }
#pragma unroll
    for (int m = 16; m; m >>= 1) ss += __shfl_xor_sync(0xffffffffu, ss, m);
    float rstd = rsqrtf(ss * (1.f / DV) + EPSR);

#pragma unroll
    for (int s = 0; s < 4; s++) {
        int dv = lane + 32 * s;
        float z = proj[(size_t)bt * IPD + CD + h * DV + dv];
        float gv = nw[dv] * v[s] * rstd * silu_f(z);
        __nv_bfloat16 hb = __float2bfloat16(gv);
        size_t idx = (size_t)bt * VD + h * DV + dv;
        gh[idx] = hb;
        gl[idx] = __float2bfloat16(gv - __bfloat162float(hb));
    }
}

// ---------------- launch ----------------
extern "C" void kernel_launch(void* const* d_in, const int* in_sizes, int n_in,
                              void* d_out, int out_size)
{
    const float* x          = (const float*)d_in[0];
    const float* in_proj_w  = (const float*)d_in[2];
    const float* conv_w     = (const float*)d_in[3];
    const float* dt_bias    = (const float*)d_in[4];
    const float* A_log      = (const float*)d_in[5];
    const float* norm_w     = (const float*)d_in[6];
    const float* out_proj_w = (const float*)d_in[7];
    float* out = (float*)d_out;

    float *proj, *q, *k, *v, *beta, *gdec, *o;
    __nv_bfloat16 *xh, *xl, *wih, *wil, *woh, *wol, *gh, *gl;
    cudaGetSymbolAddress((void**)&proj, g_proj);
    cudaGetSymbolAddress((void**)&q,    g_q);
    cudaGetSymbolAddress((void**)&k,    g_k);
    cudaGetSymbolAddress((void**)&v,    g_v);
    cudaGetSymbolAddress((void**)&beta, g_beta);
    cudaGetSymbolAddress((void**)&gdec, g_gdec);
    cudaGetSymbolAddress((void**)&o,    g_o);
    cudaGetSymbolAddress((void**)&xh,  g_xh);
    cudaGetSymbolAddress((void**)&xl,  g_xl);
    cudaGetSymbolAddress((void**)&wih, g_wih);
    cudaGetSymbolAddress((void**)&wil, g_wil);
    cudaGetSymbolAddress((void**)&woh, g_woh);
    cudaGetSymbolAddress((void**)&wol, g_wol);
    cudaGetSymbolAddress((void**)&gh,  g_gh);
    cudaGetSymbolAddress((void**)&gl,  g_gl);

    cudaFuncSetAttribute(gemm_bf16split_kernel, cudaFuncAttributeMaxDynamicSharedMemorySize, GSMEM);
    cudaFuncSetAttribute(chunk_prep_kernel, cudaFuncAttributeMaxDynamicSharedMemorySize, PA_SMEM);
    cudaFuncSetAttribute(chunk_scan_kernel, cudaFuncAttributeMaxDynamicSharedMemorySize, SC_SMEM);

    // 0) fp32 -> bf16 hi/lo splits (single fused launch)
    split_all_kernel<<<(NSPLIT + 255) / 256, 256>>>(x, in_proj_w, out_proj_w);

    // 1) in_proj on tensor cores
    gemm_bf16split_kernel<<<dim3((IPD + 127) / 128, BT / 128), 256, GSMEM>>>(
        xh, xl, wih, wil, proj, BT, IPD, HID);

    // 2) conv + activations
    conv_qk_kernel<<<BT, 512>>>(proj, conv_w, A_log, dt_bias, q, k, beta, gdec);
    conv_v_kernel<<<(BT * VD) / 256, 256>>>(proj, conv_w, v);

    // 3) chunked delta-rule recurrence
    chunk_prep_kernel<<<NU, 256, PA_SMEM>>>(q, k, v, gdec, beta);
    chunk_scan_kernel<<<BB * NVH * 4, 256, SC_SMEM>>>(o);

    // 4) norm/gate + out_proj on tensor cores
    gate_kernel<<<(BT * NVH) / 8, 256>>>(o, proj, norm_w, gh, gl);
    gemm_bf16split_kernel<<<dim3(HID / 128, BT / 128), 256, GSMEM>>>(
        gh, gl, woh, wol, out, BT, HID, VD);
}

// round 17
// speedup vs baseline: 1.1040x; 1.1040x over previous
#include <cuda_runtime.h>
#include <cuda_bf16.h>
#include <math.h>
#include <stdint.h>

// ---------------- problem constants ----------------
#define BB   2
#define TT   1024
#define HID  2048
#define NKH  8
#define NVH  16
#define DK   64
#define DV   128
#define KSZ  4
#define KD   (NKH*DK)          // 512
#define VD   (NVH*DV)          // 2048
#define CD   (2*KD + VD)       // 3072
#define IPD  (CD + VD + 2*NVH) // 5152
#define BT   (BB*TT)           // 2048
#define EPSR 1e-6f
#define SCALE 0.125f           // DK^-0.5
#define CS   64                // chunk size
#define NCH  (TT/CS)           // 16 chunks per sequence
#define NU   (BB*NVH*NCH)      // 512 units

// ---------------- scratch (__device__ globals; no allocs allowed) ----------------
__device__ float g_proj [(size_t)BT * IPD];
__device__ float g_q    [(size_t)BT * KD];
__device__ float g_k    [(size_t)BT * KD];
__device__ float g_v    [(size_t)BT * VD];
__device__ float g_beta [(size_t)BT * NVH];
__device__ float g_gdec [(size_t)BT * NVH];
__device__ float g_o    [(size_t)BT * VD];

// chunked-recurrence precomputed operands (per unit u = (b,h,c))
__device__ float g_kgt [(size_t)NU * 4096];   // [k][i] = k_i[k] * e^{G_i}
__device__ float g_tbt [(size_t)NU * 4096];   // [j][i] = T_ij * beta_j
__device__ float g_aqt [(size_t)NU * 4096];   // [i][j] = SCALE*(q_i.k_j)e^{Gi-Gj}, j<=i
__device__ float g_qgt [(size_t)NU * 4096];   // [k][i] = SCALE * q_i[k] * e^{G_i}
__device__ float g_kcm [(size_t)NU * 4096];   // [j][k] = k_j[k] * e^{G_C - G_j}
__device__ float g_tvm [(size_t)NU * 8192];   // [i][v] = (T B V)[i][v]
__device__ float g_egc [NU];

// bf16 hi/lo split operands for tensor-core GEMMs
__device__ __nv_bfloat16 g_xh [(size_t)BT * HID];
__device__ __nv_bfloat16 g_xl [(size_t)BT * HID];
__device__ __nv_bfloat16 g_wih[(size_t)IPD * HID];
__device__ __nv_bfloat16 g_wil[(size_t)IPD * HID];
__device__ __nv_bfloat16 g_woh[(size_t)HID * VD];
__device__ __nv_bfloat16 g_wol[(size_t)HID * VD];
__device__ __nv_bfloat16 g_gh [(size_t)BT * VD];
__device__ __nv_bfloat16 g_gl [(size_t)BT * VD];

__device__ __forceinline__ float silu_f(float x) { return x / (1.f + expf(-x)); }

// ---------------- packed f32x2 helpers ----------------
__device__ __forceinline__ unsigned long long pack2(float lo, float hi) {
    unsigned long long r;
    asm("mov.b64 %0, {%1, %2};" : "=l"(r) : "f"(lo), "f"(hi));
    return r;
}
__device__ __forceinline__ void ffma2(unsigned long long &d, unsigned long long a, unsigned long long b) {
    asm("fma.rn.f32x2 %0, %1, %2, %0;" : "+l"(d) : "l"(a), "l"(b));
}
__device__ __forceinline__ float lo2(unsigned long long v) { return __uint_as_float((unsigned)(v & 0xffffffffull)); }
__device__ __forceinline__ float hi2(unsigned long long v) { return __uint_as_float((unsigned)(v >> 32)); }

// ---------------- HMMA / ldmatrix / cp.async helpers (sm_80+ ISA) ----------------
__device__ __forceinline__ uint32_t smem_u32(const void* p) {
    uint32_t a;
    asm("{ .reg .u64 t; cvta.to.shared.u64 t, %1; cvt.u32.u64 %0, t; }" : "=r"(a) : "l"(p));
    return a;
}
__device__ __forceinline__ void ldsm_x4(uint32_t* r, uint32_t addr) {
    asm volatile("ldmatrix.sync.aligned.m8n8.x4.shared.b16 {%0,%1,%2,%3}, [%4];"
        : "=r"(r[0]), "=r"(r[1]), "=r"(r[2]), "=r"(r[3]) : "r"(addr));
}
__device__ __forceinline__ void mma_bf16(float* c, const uint32_t* a, const uint32_t* b) {
    asm volatile(
        "mma.sync.aligned.m16n8k16.row.col.f32.bf16.bf16.f32 "
        "{%0,%1,%2,%3}, {%4,%5,%6,%7}, {%8,%9}, {%0,%1,%2,%3};"
        : "+f"(c[0]), "+f"(c[1]), "+f"(c[2]), "+f"(c[3])
        : "r"(a[0]), "r"(a[1]), "r"(a[2]), "r"(a[3]), "r"(b[0]), "r"(b[1]));
}
__device__ __forceinline__ void cpa16(uint32_t dst, const void* src) {
    asm volatile("cp.async.cg.shared.global [%0], [%1], 16;" :: "r"(dst), "l"(src));
}
#define CP_COMMIT() asm volatile("cp.async.commit_group;" ::: "memory")
#define CP_WAIT2()  asm volatile("cp.async.wait_group 2;" ::: "memory")
#define CP_WAIT1()  asm volatile("cp.async.wait_group 1;" ::: "memory")
#define CP_WAIT0()  asm volatile("cp.async.wait_group 0;" ::: "memory")

// ============ fp32 -> bf16 hi/lo split (fused: x, in_proj_w, out_proj_w) ============
#define NX  (BT*HID)
#define NWI (IPD*HID)
#define NWO (HID*VD)
#define NSPLIT (NX + NWI + NWO)

__global__ __launch_bounds__(256)
void split_all_kernel(const float* __restrict__ x, const float* __restrict__ wi,
                      const float* __restrict__ wo)
{
    int i = blockIdx.x * blockDim.x + threadIdx.x;
    const float* src;
    __nv_bfloat16 *hi, *lo;
    int off;
    if (i < NX)            { src = x;  hi = g_xh;  lo = g_xl;  off = i; }
    else if (i < NX + NWI) { src = wi; hi = g_wih; lo = g_wil; off = i - NX; }
    else if (i < NSPLIT)   { src = wo; hi = g_woh; lo = g_wol; off = i - NX - NWI; }
    else return;
    float v = src[off];
    __nv_bfloat16 h = __float2bfloat16(v);
    hi[off] = h;
    lo[off] = __float2bfloat16(v - __bfloat162float(h));
}

// ============ tensor-core GEMM: C[M,N] = A[M,K] @ B[N,K]^T (bf16 hi/lo split) ============
// tile 128x128x32, 8 warps (32m x 64n each), 3-stage cp.async pipeline,
// XOR-swizzled 64B-row smem stages (32KB/stage). 2 CTAs/SM. [R15-proven]
#define MTS    8192
#define OFF_AH 0
#define OFF_AL MTS
#define OFF_BH (2*MTS)
#define OFF_BL (3*MTS)
#define STG    (4*MTS)
#define NSTG   3
#define GSMEM  (NSTG*STG)                // 98304 B

__device__ __forceinline__ uint32_t swz(int r, int c) {
    return (uint32_t)(r * 64 + ((c ^ ((r >> 1) & 3)) * 16));
}

__global__ __launch_bounds__(256, 2)
void gemm_bf16split_kernel(const __nv_bfloat16* __restrict__ Ah, const __nv_bfloat16* __restrict__ Al,
                           const __nv_bfloat16* __restrict__ Bh, const __nv_bfloat16* __restrict__ Bl,
                           float* __restrict__ C, int M, int N, int K)
{
    extern __shared__ __align__(128) char smem[];
    const uint32_t sbase = smem_u32(smem);
    const int tid  = threadIdx.x;
    const int wid  = tid >> 5, lane = tid & 31;
    const int bm = blockIdx.y * 128;
    const int bn = blockIdx.x * 128;
    const int wm = (wid & 3) * 32;
    const int wn = (wid >> 2) * 64;

    float acc[2][8][4];
#pragma unroll
    for (int i = 0; i < 2; i++)
#pragma unroll
        for (int j = 0; j < 8; j++)
#pragma unroll
            for (int c = 0; c < 4; c++) acc[i][j][c] = 0.f;

    const int ns = K / 32;

    auto load_stage = [&](int buf, int kbase) {
        const uint32_t sb0 = sbase + buf * STG;
#pragma unroll
        for (int it = 0; it < 2; it++) {
            int idx = tid + 256 * it;
            int row = idx >> 2, c = idx & 3;
            uint32_t soff = swz(row, c);
            const size_t ao = (size_t)(bm + row) * K + kbase + c * 8;
            cpa16(sb0 + OFF_AH + soff, Ah + ao);
            cpa16(sb0 + OFF_AL + soff, Al + ao);
            int br = bn + row; if (br >= N) br = 0;
            const size_t bo = (size_t)br * K + kbase + c * 8;
            cpa16(sb0 + OFF_BH + soff, Bh + bo);
            cpa16(sb0 + OFF_BL + soff, Bl + bo);
        }
    };

    load_stage(0, 0);  CP_COMMIT();
    load_stage(1, 32); CP_COMMIT();
    load_stage(2, 64); CP_COMMIT();

    const int arow  = lane & 15;
    const int acol8 = (lane >> 4) * 8;
    const int brow  = (lane & 7) + ((lane >> 4) & 1) * 8;
    const int bcol8 = ((lane >> 3) & 1) * 8;

    int buf = 0;
    for (int s = 0; s < ns; s++) {
        CP_WAIT2();
        __syncthreads();
        const uint32_t sb0 = sbase + buf * STG;
        const uint32_t sah = sb0 + OFF_AH, sal = sb0 + OFF_AL;
        const uint32_t sbh = sb0 + OFF_BH, sbl = sb0 + OFF_BL;

#pragma unroll
        for (int ks = 0; ks < 32; ks += 16) {
            uint32_t ah[2][4], al[2][4];
#pragma unroll
            for (int mt = 0; mt < 2; mt++) {
                int r = wm + mt * 16 + arow;
                uint32_t aoff = swz(r, (ks + acol8) >> 3);
                ldsm_x4(ah[mt], sah + aoff);
                ldsm_x4(al[mt], sal + aoff);
            }
#pragma unroll
            for (int ng = 0; ng < 4; ng++) {
                uint32_t bh[4], bl[4];
                int rb = wn + ng * 16 + brow;
                uint32_t boff = swz(rb, (ks + bcol8) >> 3);
                ldsm_x4(bh, sbh + boff);
                ldsm_x4(bl, sbl + boff);
#pragma unroll
                for (int mt = 0; mt < 2; mt++) {
                    float* c0 = acc[mt][ng * 2 + 0];
                    float* c1 = acc[mt][ng * 2 + 1];
                    mma_bf16(c0, ah[mt], bh + 0);
                    mma_bf16(c0, ah[mt], bl + 0);
                    mma_bf16(c0, al[mt], bh + 0);
                    mma_bf16(c1, ah[mt], bh + 2);
                    mma_bf16(c1, ah[mt], bl + 2);
                    mma_bf16(c1, al[mt], bh + 2);
                }
            }
        }
        __syncthreads();
        if (s + 3 < ns) load_stage(buf, (s + 3) * 32);
        CP_COMMIT();
        if (++buf == NSTG) buf = 0;
    }

#pragma unroll
    for (int mt = 0; mt < 2; mt++) {
        int r0 = bm + wm + mt * 16 + (lane >> 2);
        int r1 = r0 + 8;
#pragma unroll
        for (int nt = 0; nt < 8; nt++) {
            int col = bn + wn + nt * 8 + (lane & 3) * 2;
            if (col < N) {
                float* a = acc[mt][nt];
                *(float2*)(C + (size_t)r0 * N + col) = make_float2(a[0], a[1]);
                *(float2*)(C + (size_t)r1 * N + col) = make_float2(a[2], a[3]);
            }
        }
    }
}

// ============ fused conv: q/k (silu+l2norm) + v (silu) + beta/g scalars ============
// one 512-thread block per (b,t); warps 0..7 q heads, 8..15 k heads; each
// thread additionally computes 4 v channels (stride 512, coalesced).
__global__ __launch_bounds__(512)
void conv_all_kernel(const float* __restrict__ proj, const float* __restrict__ conv_w,
                     const float* __restrict__ A_log, const float* __restrict__ dt_bias,
                     float* __restrict__ qo, float* __restrict__ ko,
                     float* __restrict__ vo,
                     float* __restrict__ beta_o, float* __restrict__ g_o_)
{
    const int bt = blockIdx.x;
    const int t  = bt & (TT - 1);
    const int warp = threadIdx.x >> 5, lane = threadIdx.x & 31;

    // ---- q/k channels ----
    float r[2];
#pragma unroll
    for (int s = 0; s < 2; s++) {
        int ch = warp * 64 + s * 32 + lane;
        float acc = 0.f;
#pragma unroll
        for (int kk = 0; kk < KSZ; kk++) {
            int tt = t - 3 + kk;
            float xv = (tt >= 0) ? proj[(size_t)(bt - 3 + kk) * IPD + ch] : 0.f;
            acc = fmaf(xv, conv_w[ch * KSZ + kk], acc);
        }
        r[s] = silu_f(acc);
    }
    float ss = r[0]*r[0] + r[1]*r[1];
#pragma unroll
    for (int o = 16; o; o >>= 1) ss += __shfl_xor_sync(0xffffffffu, ss, o);
    float inv = 1.f / fmaxf(sqrtf(ss), 1e-12f);

    if (warp < 8) {
        float* dst = qo + ((size_t)bt * NKH + warp) * DK;
        dst[lane] = r[0] * inv; dst[lane + 32] = r[1] * inv;
    } else {
        float* dst = ko + ((size_t)bt * NKH + (warp - 8)) * DK;
        dst[lane] = r[0] * inv; dst[lane + 32] = r[1] * inv;
    }

    // ---- v channels (4 per thread, stride 512) ----
#pragma unroll
    for (int s = 0; s < 4; s++) {
        int cv = threadIdx.x + s * 512;
        int ch = 2 * KD + cv;
        float acc = 0.f;
#pragma unroll
        for (int kk = 0; kk < KSZ; kk++) {
            int tt = t - 3 + kk;
            float xv = (tt >= 0) ? proj[(size_t)(bt - 3 + kk) * IPD + ch] : 0.f;
            acc = fmaf(xv, conv_w[ch * KSZ + kk], acc);
        }
        vo[(size_t)bt * VD + cv] = silu_f(acc);
    }

    // ---- scalars ----
    if (threadIdx.x < NVH) {
        int h = threadIdx.x;
        float braw = proj[(size_t)bt * IPD + CD + VD + h];
        float araw = proj[(size_t)bt * IPD + CD + VD + NVH + h];
        beta_o[bt * NVH + h] = 1.f / (1.f + expf(-braw));
        float si = araw + dt_bias[h];
        float sp = (si > 20.f) ? si : log1pf(expf(si));
        g_o_[bt * NVH + h] = -expf(A_log[h]) * sp;
    }
}

// ============ Phase A: per-(b,h,chunk) precompute (fully parallel) [proven] ============
#define PA_SMEM (20864 * 4)

__global__ __launch_bounds__(256)
void chunk_prep_kernel(const float* __restrict__ qarr, const float* __restrict__ karr,
                       const float* __restrict__ varr, const float* __restrict__ garr,
                       const float* __restrict__ barr)
{
    extern __shared__ __align__(16) float sm[];
    float* KT   = sm;
    float* QT   = sm + 4096;
    float* Lm   = sm + 8192;
    float* Tm   = sm + 12352;
    float* TBTs = sm + 16512;
    float* gsh  = sm + 20608;
    float* bsh  = sm + 20672;
    float* Gs   = sm + 20736;
    float* egs  = sm + 20800;
    float* Vs   = sm;

    const int u  = blockIdx.x;
    const int c  = u & 15;
    const int h  = (u >> 4) & 15;
    const int b  = u >> 8;
    const int kh = h >> 1;
    const int t0 = b * TT + c * CS;
    const int tid = threadIdx.x;
    const size_t ub  = (size_t)u * 4096;
    const size_t ub2 = (size_t)u * 8192;

    {
        int i = tid & 63, kq = (tid >> 6) * 16;
        const float* krow = karr + ((size_t)(t0 + i) * NKH + kh) * DK;
        const float* qrow = qarr + ((size_t)(t0 + i) * NKH + kh) * DK;
#pragma unroll
        for (int m = 0; m < 16; m += 4) {
            float4 kv = *(const float4*)(krow + kq + m);
            float4 qv = *(const float4*)(qrow + kq + m);
            KT[(kq+m+0)*64 + i] = kv.x; KT[(kq+m+1)*64 + i] = kv.y;
            KT[(kq+m+2)*64 + i] = kv.z; KT[(kq+m+3)*64 + i] = kv.w;
            QT[(kq+m+0)*64 + i] = qv.x; QT[(kq+m+1)*64 + i] = qv.y;
            QT[(kq+m+2)*64 + i] = qv.z; QT[(kq+m+3)*64 + i] = qv.w;
        }
        if (tid < 64) {
            gsh[tid] = garr[(size_t)(t0 + tid) * NVH + h];
            bsh[tid] = barr[(size_t)(t0 + tid) * NVH + h];
        }
    }
    __syncthreads();
    if (tid == 0) {
        float s = 0.f;
        for (int i = 0; i < 64; i++) { s += gsh[i]; Gs[i] = s; }
    }
    __syncthreads();
    if (tid < 64) egs[tid] = expf(Gs[tid]);
    __syncthreads();

    const int ty = tid >> 4, tx = tid & 15;

    {
        float mm[16], aq[16];
#pragma unroll
        for (int z = 0; z < 16; z++) { mm[z] = 0.f; aq[z] = 0.f; }
        for (int k = 0; k < 64; k++) {
            float4 ka = *(const float4*)&KT[k*64 + 4*ty];
            float4 kb = *(const float4*)&KT[k*64 + 4*tx];
            float4 qa = *(const float4*)&QT[k*64 + 4*ty];
#pragma unroll
            for (int r2 = 0; r2 < 4; r2++) {
                float av = (&ka.x)[r2], qv = (&qa.x)[r2];
                mm[r2*4+0] = fmaf(av, kb.x, mm[r2*4+0]);
                mm[r2*4+1] = fmaf(av, kb.y, mm[r2*4+1]);
                mm[r2*4+2] = fmaf(av, kb.z, mm[r2*4+2]);
                mm[r2*4+3] = fmaf(av, kb.w, mm[r2*4+3]);
                aq[r2*4+0] = fmaf(qv, kb.x, aq[r2*4+0]);
                aq[r2*4+1] = fmaf(qv, kb.y, aq[r2*4+1]);
                aq[r2*4+2] = fmaf(qv, kb.z, aq[r2*4+2]);
                aq[r2*4+3] = fmaf(qv, kb.w, aq[r2*4+3]);
            }
        }
#pragma unroll
        for (int r2 = 0; r2 < 4; r2++) {
            int i = 4*ty + r2;
            float ov[4];
#pragma unroll
            for (int c2 = 0; c2 < 4; c2++) {
                int j = 4*tx + c2;
                float e = expf(fminf(Gs[i] - Gs[j], 0.f));
                Lm[i*65 + j] = (j < i) ? bsh[i] * mm[r2*4+c2] * e : 0.f;
                ov[c2] = (j <= i) ? SCALE * aq[r2*4+c2] * e : 0.f;
            }
            *(float4*)&g_aqt[ub + (size_t)i*64 + 4*tx] = make_float4(ov[0], ov[1], ov[2], ov[3]);
        }
    }

    {
        int i = tid & 63, kq = (tid >> 6) * 16;
        float ei = egs[i];
#pragma unroll
        for (int m = 0; m < 16; m++) {
            g_kgt[ub + (size_t)(kq+m)*64 + i] = KT[(kq+m)*64 + i] * ei;
            g_qgt[ub + (size_t)(kq+m)*64 + i] = QT[(kq+m)*64 + i] * (SCALE * ei);
        }
        int j = tid >> 2, kq2 = (tid & 3) * 16;
        float sc2 = expf(Gs[63] - Gs[j]);
        const float* krow = karr + ((size_t)(t0 + j) * NKH + kh) * DK;
#pragma unroll
        for (int m = 0; m < 16; m += 4) {
            float4 kv = *(const float4*)(krow + kq2 + m);
            *(float4*)&g_kcm[ub + (size_t)j*64 + kq2 + m] =
                make_float4(kv.x * sc2, kv.y * sc2, kv.z * sc2, kv.w * sc2);
        }
        if (tid == 0) g_egc[u] = expf(Gs[63]);
    }

    for (int idx = tid; idx < 4096; idx += 256) {
        int i = idx >> 6, j = idx & 63;
        Tm[i*65 + j] = (i == j) ? 1.f : 0.f;
    }
    for (int r = 0; r < 63; r++) {
        __syncthreads();
        int i = r + 1 + (tid >> 2);
        if (i < 64) {
            float lir = Lm[i*65 + r];
            for (int j = (tid & 3); j <= r; j += 4)
                Tm[i*65 + j] -= lir * Tm[r*65 + j];
        }
    }
    __syncthreads();

    {
        int i = tid & 63, jq = (tid >> 6) * 16;
#pragma unroll
        for (int m = 0; m < 16; m++) {
            int j = jq + m;
            float tv = Tm[i*65 + j] * bsh[j];
            TBTs[j*64 + i] = tv;
            g_tbt[ub + (size_t)j*64 + i] = tv;
        }
    }
    __syncthreads();

    {
        int j = tid >> 1, v0 = (tid & 1) * 64;
        const float* vrow = varr + (size_t)(t0 + j) * VD + h * DV + v0;
#pragma unroll
        for (int m = 0; m < 64; m += 4) {
            *(float4*)&Vs[j*128 + v0 + m] = *(const float4*)(vrow + m);
        }
    }
    __syncthreads();

    for (int half = 0; half < 2; half++) {
        float acc[16];
#pragma unroll
        for (int z = 0; z < 16; z++) acc[z] = 0.f;
        for (int j = 0; j < 64; j++) {
            float4 a = *(const float4*)&TBTs[j*64 + 4*ty];
            float4 bv = *(const float4*)&Vs[j*128 + half*64 + 4*tx];
#pragma unroll
            for (int r2 = 0; r2 < 4; r2++) {
                float av = (&a.x)[r2];
                acc[r2*4+0] = fmaf(av, bv.x, acc[r2*4+0]);
                acc[r2*4+1] = fmaf(av, bv.y, acc[r2*4+1]);
                acc[r2*4+2] = fmaf(av, bv.z, acc[r2*4+2]);
                acc[r2*4+3] = fmaf(av, bv.w, acc[r2*4+3]);
            }
        }
#pragma unroll
        for (int r2 = 0; r2 < 4; r2++) {
            int i = 4*ty + r2;
            *(float4*)&g_tvm[ub2 + (size_t)i*128 + half*64 + 4*tx] =
                make_float4(acc[r2*4+0], acc[r2*4+1], acc[r2*4+2], acc[r2*4+3]);
        }
    }
}

// ============ Phase B: chunk scan, fused 3 passes, 5 operand slots [R15-proven] ============
#define SC_SMEM ((2048*4 + 4096*3 + 4352 + 4096) * 4)

__global__ __launch_bounds__(256)
void chunk_scan_kernel(float* __restrict__ oarr)
{
    extern __shared__ __align__(16) float ssm[];
    float* Ssh  = ssm;
    float* Wsh  = ssm + 2048;
    float* Dsh  = ssm + 4096;
    float* TVsh = ssm + 6144;
    float* SA   = ssm + 8192;
    float* SB   = ssm + 12288;
    float* SC   = ssm + 16384;
    float* SD   = ssm + 20480;
    float* SE   = ssm + 24832;

    const int bid = blockIdx.x;
    const int vs = bid & 3;
    const int h  = (bid >> 2) & 15;
    const int b  = bid >> 6;
    const int v0 = vs * 32;
    const int tid = threadIdx.x;
    const int ty = tid >> 3;
    const int tx = tid & 7;

    auto stage64 = [&](float* dst, const float* src) {
        uint32_t d = smem_u32(dst);
#pragma unroll
        for (int r = 0; r < 4; r++) { int id = tid + 256*r; cpa16(d + id*16, src + (size_t)id*4); }
    };
    auto stage68 = [&](float* dst, const float* src) {
        uint32_t d = smem_u32(dst);
#pragma unroll
        for (int r = 0; r < 4; r++) {
            int id = tid + 256*r; int row = id >> 4, cc = id & 15;
            cpa16(d + (row*68 + cc*4)*4, src + (size_t)id*4);
        }
    };
    auto stageTV = [&](const float* src) {
        uint32_t d = smem_u32(TVsh);
#pragma unroll
        for (int r = 0; r < 2; r++) {
            int id = tid + 256*r; int row = id >> 3, cc = id & 7;
            cpa16(d + id*16, src + (size_t)row*128 + cc*4);
        }
    };

    for (int idx = tid; idx < 2048; idx += 256) Ssh[idx] = 0.f;

    const size_t ubase = (size_t)(((b << 4) | h) << 4) * 4096;
    const size_t ub2base = ubase * 2;

    stage64(SA, g_kgt + ubase);
    stage64(SB, g_qgt + ubase);
    CP_COMMIT();
    stage64(SC, g_tbt + ubase);
    stageTV(g_tvm + ub2base + v0);
    CP_COMMIT();
    stage68(SD, g_aqt + ubase);
    stage64(SE, g_kcm + ubase);
    CP_COMMIT();

    for (int c = 0; c < NCH; c++) {
        const size_t u    = (size_t)((((b << 4) | h) << 4) | c);
        const size_t ubn  = (u + 1) * 4096;
        const size_t ub2n = (u + 1) * 8192;
        const bool more = (c + 1 < NCH);

        CP_WAIT2();
        __syncthreads();

        unsigned long long o00=0,o01=0,o10=0,o11=0;
        {
            unsigned long long w00=0,w01=0,w10=0,w11=0;
            for (int k = 0; k < 64; k++) {
                float2 kg = *(const float2*)&SA[k*64 + 2*ty];
                float2 qg = *(const float2*)&SB[k*64 + 2*ty];
                const unsigned long long* bp = (const unsigned long long*)&Ssh[k*32 + 4*tx];
                unsigned long long s0 = bp[0], s1 = bp[1];
                unsigned long long kx = pack2(kg.x, kg.x), ky = pack2(kg.y, kg.y);
                unsigned long long qx = pack2(qg.x, qg.x), qy = pack2(qg.y, qg.y);
                ffma2(w00, kx, s0); ffma2(w01, kx, s1);
                ffma2(w10, ky, s0); ffma2(w11, ky, s1);
                ffma2(o00, qx, s0); ffma2(o01, qx, s1);
                ffma2(o10, qy, s0); ffma2(o11, qy, s1);
            }
            unsigned long long* w0 = (unsigned long long*)&Wsh[(2*ty)*32 + 4*tx];
            unsigned long long* w1 = (unsigned long long*)&Wsh[(2*ty+1)*32 + 4*tx];
            w0[0]=w00; w0[1]=w01; w1[0]=w10; w1[1]=w11;
        }

        CP_WAIT1();
        __syncthreads();
        if (more) { stage64(SA, g_kgt + ubn); stage64(SB, g_qgt + ubn); }
        CP_COMMIT();

        {
            unsigned long long a00=0,a01=0,a10=0,a11=0;
            for (int k = 0; k < 64; k++) {
                float2 tb = *(const float2*)&SC[k*64 + 2*ty];
                const unsigned long long* bp = (const unsigned long long*)&Wsh[k*32 + 4*tx];
                unsigned long long b0 = bp[0], b1 = bp[1];
                unsigned long long ax = pack2(tb.x, tb.x), ay = pack2(tb.y, tb.y);
                ffma2(a00, ax, b0); ffma2(a01, ax, b1);
                ffma2(a10, ay, b0); ffma2(a11, ay, b1);
            }
            float4 t0 = *(const float4*)&TVsh[(2*ty)*32 + 4*tx];
            float4 t1 = *(const float4*)&TVsh[(2*ty+1)*32 + 4*tx];
            *(float4*)&Dsh[(2*ty)*32 + 4*tx] =
                make_float4(t0.x - lo2(a00), t0.y - hi2(a00), t0.z - lo2(a01), t0.w - hi2(a01));
            *(float4*)&Dsh[(2*ty+1)*32 + 4*tx] =
                make_float4(t1.x - lo2(a10), t1.y - hi2(a10), t1.z - lo2(a11), t1.w - hi2(a11));
        }

        CP_WAIT1();
        __syncthreads();
        if (more) { stage64(SC, g_tbt + ubn); stageTV(g_tvm + ub2n + v0); }
        CP_COMMIT();

        {
            unsigned long long s00=0,s01=0,s10=0,s11=0;
            for (int j = 0; j < 64; j++) {
                float aq0 = SD[(2*ty)*68 + j];
                float aq1 = SD[(2*ty+1)*68 + j];
                float2 kc = *(const float2*)&SE[j*64 + 2*ty];
                const unsigned long long* bp = (const unsigned long long*)&Dsh[j*32 + 4*tx];
                unsigned long long d0 = bp[0], d1 = bp[1];
                unsigned long long a0 = pack2(aq0, aq0), a1 = pack2(aq1, aq1);
                unsigned long long k0 = pack2(kc.x, kc.x), k1 = pack2(kc.y, kc.y);
                ffma2(o00, a0, d0); ffma2(o01, a0, d1);
                ffma2(o10, a1, d0); ffma2(o11, a1, d1);
                ffma2(s00, k0, d0); ffma2(s01, k0, d1);
                ffma2(s10, k1, d0); ffma2(s11, k1, d1);
            }
            int trow = b * TT + c * CS + 2*ty;
            *(float4*)(oarr + (size_t)trow * VD + h * DV + v0 + 4*tx) =
                make_float4(lo2(o00), hi2(o00), lo2(o01), hi2(o01));
            *(float4*)(oarr + (size_t)(trow+1) * VD + h * DV + v0 + 4*tx) =
                make_float4(lo2(o10), hi2(o10), lo2(o11), hi2(o11));

            float eg = g_egc[u];
            unsigned long long eg2 = pack2(eg, eg);
            unsigned long long* sp0 = (unsigned long long*)&Ssh[(2*ty)*32 + 4*tx];
            unsigned long long* sp1 = (unsigned long long*)&Ssh[(2*ty+1)*32 + 4*tx];
            ffma2(s00, eg2, sp0[0]); ffma2(s01, eg2, sp0[1]);
            ffma2(s10, eg2, sp1[0]); ffma2(s11, eg2, sp1[1]);
            sp0[0]=s00; sp0[1]=s01; sp1[0]=s10; sp1[1]=s11;
        }

        __syncthreads();
        if (more) { stage68(SD, g_aqt + ubn); stage64(SE, g_kcm + ubn); }
        CP_COMMIT();
    }
    CP_WAIT0();
}

// ============ RMSNorm * silu(z) gate -> bf16 hi/lo ============
__global__ __launch_bounds__(256)
void gate_kernel(const float* __restrict__ o, const float* __restrict__ proj,
                 const float* __restrict__ nw,
                 __nv_bfloat16* __restrict__ gh, __nv_bfloat16* __restrict__ gl)
{
    int gw = (blockIdx.x * blockDim.x + threadIdx.x) >> 5;
    int lane = threadIdx.x & 31;
    int h  = gw & 15;
    int bt = gw >> 4;

    const float* orow = o + (size_t)bt * VD + h * DV;
    float v[4]; float ss = 0.f;
#pragma unroll
    for (int s = 0; s < 4; s++) { v[s] = orow[lane + 32 * s]; ss = fmaf(v[s], v[s], ss); }
#pragma unroll
    for (int m = 16; m; m >>= 1) ss += __shfl_xor_sync(0xffffffffu, ss, m);
    float rstd = rsqrtf(ss * (1.f / DV) + EPSR);

#pragma unroll
    for (int s = 0; s < 4; s++) {
        int dv = lane + 32 * s;
        float z = proj[(size_t)bt * IPD + CD + h * DV + dv];
        float gv = nw[dv] * v[s] * rstd * silu_f(z);
        __nv_bfloat16 hb = __float2bfloat16(gv);
        size_t idx = (size_t)bt * VD + h * DV + dv;
        gh[idx] = hb;
        gl[idx] = __float2bfloat16(gv - __bfloat162float(hb));
    }
}

// ---------------- launch ----------------
extern "C" void kernel_launch(void* const* d_in, const int* in_sizes, int n_in,
                              void* d_out, int out_size)
{
    const float* x          = (const float*)d_in[0];
    const float* in_proj_w  = (const float*)d_in[2];
    const float* conv_w     = (const float*)d_in[3];
    const float* dt_bias    = (const float*)d_in[4];
    const float* A_log      = (const float*)d_in[5];
    const float* norm_w     = (const float*)d_in[6];
    const float* out_proj_w = (const float*)d_in[7];
    float* out = (float*)d_out;

    float *proj, *q, *k, *v, *beta, *gdec, *o;
    __nv_bfloat16 *xh, *xl, *wih, *wil, *woh, *wol, *gh, *gl;
    cudaGetSymbolAddress((void**)&proj, g_proj);
    cudaGetSymbolAddress((void**)&q,    g_q);
    cudaGetSymbolAddress((void**)&k,    g_k);
    cudaGetSymbolAddress((void**)&v,    g_v);
    cudaGetSymbolAddress((void**)&beta, g_beta);
    cudaGetSymbolAddress((void**)&gdec, g_gdec);
    cudaGetSymbolAddress((void**)&o,    g_o);
    cudaGetSymbolAddress((void**)&xh,  g_xh);
    cudaGetSymbolAddress((void**)&xl,  g_xl);
    cudaGetSymbolAddress((void**)&wih, g_wih);
    cudaGetSymbolAddress((void**)&wil, g_wil);
    cudaGetSymbolAddress((void**)&woh, g_woh);
    cudaGetSymbolAddress((void**)&wol, g_wol);
    cudaGetSymbolAddress((void**)&gh,  g_gh);
    cudaGetSymbolAddress((void**)&gl,  g_gl);

    cudaFuncSetAttribute(gemm_bf16split_kernel, cudaFuncAttributeMaxDynamicSharedMemorySize, GSMEM);
    cudaFuncSetAttribute(chunk_prep_kernel, cudaFuncAttributeMaxDynamicSharedMemorySize, PA_SMEM);
    cudaFuncSetAttribute(chunk_scan_kernel, cudaFuncAttributeMaxDynamicSharedMemorySize, SC_SMEM);

    // 0) fp32 -> bf16 hi/lo splits (single fused launch)
    split_all_kernel<<<(NSPLIT + 255) / 256, 256>>>(x, in_proj_w, out_proj_w);

    // 1) in_proj on tensor cores
    gemm_bf16split_kernel<<<dim3((IPD + 127) / 128, BT / 128), 256, GSMEM>>>(
        xh, xl, wih, wil, proj, BT, IPD, HID);

    // 2) fused conv + activations
    conv_all_kernel<<<BT, 512>>>(proj, conv_w, A_log, dt_bias, q, k, v, beta, gdec);

    // 3) chunked delta-rule recurrence
    chunk_prep_kernel<<<NU, 256, PA_SMEM>>>(q, k, v, gdec, beta);
    chunk_scan_kernel<<<BB * NVH * 4, 256, SC_SMEM>>>(o);

    // 4) norm/gate + out_proj on tensor cores
    gate_kernel<<<(BT * NVH) / 8, 256>>>(o, proj, norm_w, gh, gl);
    gemm_bf16split_kernel<<<dim3(HID / 128, BT / 128), 256, GSMEM>>>(
        gh, gl, woh, wol, out, BT, HID, VD);
}